// round 14
// baseline (speedup 1.0000x reference)
#include <cuda_runtime.h>
#include <cuda_fp16.h>
#include <cstdint>

#define BATCH 32
#define FEAT  1024
#define PROJ  256
#define NSUP  8192
#define NCLS  1000

// ---- scratch (no allocations allowed; __device__ globals) ----
__device__ float g_xq[BATCH * PROJ];
__device__ float g_lh[2 * BATCH * NSUP];         // 2 MB: per-proj-half logits
__device__ int   g_sy_is64;
// B in mma-fragment order: idx = ks*512 + half*256 + wn*128 + np*32 + lane
__device__ uint4 g_wfrag[128 * 512];             // 1 MB

__device__ __forceinline__ uint32_t smem_u32(const void* p) {
    uint32_t a;
    asm("{ .reg .u64 t; cvta.to.shared.u64 t, %1; cvt.u32.u64 %0, t; }"
        : "=r"(a) : "l"(p));
    return a;
}

__device__ __forceinline__ uint32_t hl_pack(float a) {
    __half h = __float2half_rn(a);
    __half l = __float2half_rn(a - __half2float(h));
    __half2 p = __halves2half2(h, l);
    return *(uint32_t*)&p;
}

// ---------------------------------------------------------------------------
// K_pre: one launch, three jobs.
//  blocks 0..31    : W[1024][256] -> g_wfrag, COALESCED through smem.
//                    Block handles 32 k-rows (= 4 ks groups of 8).
//  blocks 32..287  : xq = x @ W   (old k_xq2 grid(32,8) flattened)
//  block  288      : detect int64 vs int32 sy
// ---------------------------------------------------------------------------
#define WSLAB_PITCH 258   // uint32 per smem row (2-mod-32 pad)

__global__ void __launch_bounds__(256) k_pre(const float* __restrict__ W,
                                             const float* __restrict__ x,
                                             const unsigned* __restrict__ syw) {
    const int bx = blockIdx.x;
    if (bx < 32) {
        // ---- wfrag build: slab of 32 k-rows, coalesced ----
        __shared__ uint32_t hl[32 * WSLAB_PITCH];   // [k_local][n] packed (h,l)
        const int kbase = bx * 32;                  // global k of row 0
        // load + convert: 32 rows x 256 cols = 8192 floats; 2048 float4, 8/thread
#pragma unroll
        for (int it = 0; it < 8; it++) {
            int i = it * 256 + threadIdx.x;         // 0..2047
            int kl = i >> 6;                        // 0..31 (64 float4 per row)
            int nq = i & 63;                        // float4 index within row
            float4 v = *(const float4*)(W + (size_t)(kbase + kl) * PROJ + nq * 4);
            uint32_t* dst = &hl[kl * WSLAB_PITCH + nq * 4];
            dst[0] = hl_pack(v.x);
            dst[1] = hl_pack(v.y);
            dst[2] = hl_pack(v.z);
            dst[3] = hl_pack(v.w);
        }
        __syncthreads();
        // emit: 4 ks groups x 512 uint4 = 2048 uint4, 8/thread
#pragma unroll
        for (int it = 0; it < 8; it++) {
            int o    = it * 256 + threadIdx.x;      // 0..2047
            int lane = o & 31;
            int np   = (o >> 5) & 3;
            int wn   = (o >> 7) & 1;
            int hb   = (o >> 8) & 1;
            int ksl  = o >> 9;                      // 0..3 (local ks)
            int n0   = hb * 128 + wn * 64 + np * 16 + (lane >> 2);
            int k0   = ksl * 8 + (lane & 3);        // local k
            uint4 r;
            r.x = hl[k0 * WSLAB_PITCH + n0];
            r.y = hl[(k0 + 4) * WSLAB_PITCH + n0];
            r.z = hl[k0 * WSLAB_PITCH + n0 + 8];
            r.w = hl[(k0 + 4) * WSLAB_PITCH + n0 + 8];
            g_wfrag[(size_t)(bx * 4 + ksl) * 512 + (o & 511)] = r;
        }
    } else if (bx < 288) {
        // ---- xq GEMV block (identical math to old k_xq2) ----
        __shared__ float red[8][33];
        const int blk = bx - 32;             // 0..255
        const int b = blk >> 3, pc = blk & 7;
        const int lane = threadIdx.x & 31, ks = threadIdx.x >> 5;
        const int p = pc * 32 + lane;
        float a0 = 0.f, a1 = 0.f, a2 = 0.f, a3 = 0.f;
        const float* xr = x + b * FEAT + ks * 128;
        const float* wr = W + (size_t)(ks * 128) * PROJ + p;
#pragma unroll 8
        for (int k = 0; k < 128; k += 4) {
            a0 = fmaf(xr[k + 0], wr[(k + 0) * PROJ], a0);
            a1 = fmaf(xr[k + 1], wr[(k + 1) * PROJ], a1);
            a2 = fmaf(xr[k + 2], wr[(k + 2) * PROJ], a2);
            a3 = fmaf(xr[k + 3], wr[(k + 3) * PROJ], a3);
        }
        red[ks][lane] = (a0 + a1) + (a2 + a3);
        __syncthreads();
        if (ks == 0) {
            float s = 0.f;
#pragma unroll
            for (int q = 0; q < 8; q++) s += red[q][lane];
            g_xq[b * PROJ + p] = s;
        }
    } else {
        // ---- sy dtype detect ----
        __shared__ int nz;
        if (threadIdx.x == 0) nz = 0;
        __syncthreads();
        int f = 0;
        for (int i = threadIdx.x; i < 4096; i += 256)
            if (syw[2 * i + 1] != 0u) f = 1;
        if (f) atomicOr(&nz, 1);
        __syncthreads();
        if (threadIdx.x == 0) g_sy_is64 = (nz == 0) ? 1 : 0;
    }
}

// ---------------------------------------------------------------------------
// K2: sxp GEMM (HMMA fp16 2-slot K-doubling) + fused logits epilogue.
// 256 thr / 8 warps (4M x 2N), warp tile 32x64, CTA 128x128, grid (64, 2).
// Warp-private A staging (no CTA barriers in mainloop); B via LDG.128 of
// precomputed fragments.  [R11 exact]
// ---------------------------------------------------------------------------
#define BANDB  2560                   // 32 rows * 80 B per warp per stage
#define STG2B  20480                  // 8 warps * BANDB
#define TS_PITCH  132
#define XQT_OFF   67584               // 128*132*4
#define XQT_PITCH 36
#define SSQ_OFF   86016               // XQT_OFF + 128*36*4
#define DYNB      86528

__global__ void __launch_bounds__(256, 1)
k_sxp_hmma(const float* __restrict__ sx) {
    extern __shared__ __align__(16) char dyn[];

    const int tid  = threadIdx.x;
    const int lane = tid & 31;
    const int wid  = tid >> 5;
    const int wm   = wid & 3;        // M block (32 rows)
    const int wn   = wid >> 2;       // N block (64 cols)
    const int bs   = blockIdx.x * 128;
    const int bn   = blockIdx.y * 128;
    const int hb   = blockIdx.y;

    const uint32_t sbase = smem_u32(dyn);
    const uint32_t pw_u32[2] = {sbase + (uint32_t)wid * BANDB,
                                sbase + STG2B + (uint32_t)wid * BANDB};
    char* pw_ptr[2] = {dyn + wid * BANDB, dyn + STG2B + wid * BANDB};

    const int arow = lane >> 2;      // 0..7
    const int aq   = lane & 3;       // 0..3
    const float* aptr[4];
#pragma unroll
    for (int i = 0; i < 4; i++)
        aptr[i] = sx + (size_t)(bs + wm * 32 + i * 8 + arow) * FEAT + aq * 4;
    const uint32_t sts_off = (uint32_t)(arow * 80 + aq * 16);

    const uint4* bbase = g_wfrag + hb * 256 + wn * 128 + lane;

    float c[2][8][4];
#pragma unroll
    for (int t = 0; t < 2; t++)
#pragma unroll
        for (int n = 0; n < 8; n++)
#pragma unroll
            for (int e = 0; e < 4; e++) c[t][n][e] = 0.f;

    const int grp  = lane >> 3;
    const int rsel = lane & 7;
    const int a_row_off = ((grp & 1) << 3) + rsel;
    const int a_u_off   = (grp >> 1) & 1;

    auto expand = [](float4 v) -> uint4 {
        __half h0 = __float2half_rn(v.x), h1 = __float2half_rn(v.y);
        __half h2 = __float2half_rn(v.z), h3 = __float2half_rn(v.w);
        __half2 p0 = __halves2half2(h0, __float2half_rn(v.x - __half2float(h0)));
        __half2 p1 = __halves2half2(h1, __float2half_rn(v.y - __half2float(h1)));
        __half2 p2 = __halves2half2(h2, __float2half_rn(v.z - __half2float(h2)));
        __half2 p3 = __halves2half2(h3, __float2half_rn(v.w - __half2float(h3)));
        return make_uint4(*(uint32_t*)&p0, *(uint32_t*)&p1,
                          *(uint32_t*)&p2, *(uint32_t*)&p3);
    };

    uint4 bcur[2][4];    // [ks][np]

    // ---- prologue: chunk 0 into stage 0 ----
    {
        float4 av[4];
#pragma unroll
        for (int i = 0; i < 4; i++) av[i] = *(const float4*)(aptr[i]);
#pragma unroll
        for (int i = 0; i < 4; i++)
            *(uint4*)(pw_ptr[0] + i * 8 * 80 + sts_off) = expand(av[i]);
#pragma unroll
        for (int ks = 0; ks < 2; ks++)
#pragma unroll
            for (int np = 0; np < 4; np++)
                bcur[ks][np] = bbase[ks * 512 + np * 32];
    }
    __syncwarp();

#pragma unroll 2
    for (int ch = 0; ch < 64; ch++) {
        const int s = ch & 1;
        float4 av[4];
        uint4  bnx[2][4];
        if (ch < 63) {
            const int k0 = (ch + 1) * 16;
#pragma unroll
            for (int i = 0; i < 4; i++)
                av[i] = *(const float4*)(aptr[i] + k0);
#pragma unroll
            for (int ks = 0; ks < 2; ks++)
#pragma unroll
                for (int np = 0; np < 4; np++)
                    bnx[ks][np] = bbase[(2 * (ch + 1) + ks) * 512 + np * 32];
        }

        // ---- compute on stage s: 2 ksteps of 16 expanded k ----
#pragma unroll
        for (int ks = 0; ks < 2; ks++) {
            uint32_t af[2][4];
#pragma unroll
            for (int t = 0; t < 2; t++) {
                int row = t * 16 + a_row_off;
                uint32_t addr = pw_u32[s] + (uint32_t)(row * 80 + (2 * ks + a_u_off) * 16);
                asm volatile(
                    "ldmatrix.sync.aligned.m8n8.x4.shared.b16 {%0,%1,%2,%3}, [%4];"
                    : "=r"(af[t][0]), "=r"(af[t][1]), "=r"(af[t][2]), "=r"(af[t][3])
                    : "r"(addr));
            }
#pragma unroll
            for (int t = 0; t < 2; t++)
#pragma unroll
                for (int nf = 0; nf < 8; nf++) {
                    const uint4& bq = bcur[ks][nf >> 1];
                    uint32_t b0 = (nf & 1) ? bq.z : bq.x;
                    uint32_t b1 = (nf & 1) ? bq.w : bq.y;
                    asm volatile(
                        "mma.sync.aligned.m16n8k16.row.col.f32.f16.f16.f32 "
                        "{%0,%1,%2,%3}, {%4,%5,%6,%7}, {%8,%9}, {%0,%1,%2,%3};"
                        : "+f"(c[t][nf][0]), "+f"(c[t][nf][1]),
                          "+f"(c[t][nf][2]), "+f"(c[t][nf][3])
                        : "r"(af[t][0]), "r"(af[t][1]), "r"(af[t][2]), "r"(af[t][3]),
                          "r"(b0), "r"(b1));
                }
        }

        if (ch < 63) {
            const int ns = s ^ 1;
#pragma unroll
            for (int i = 0; i < 4; i++)
                *(uint4*)(pw_ptr[ns] + i * 8 * 80 + sts_off) = expand(av[i]);
#pragma unroll
            for (int ks = 0; ks < 2; ks++)
#pragma unroll
                for (int np = 0; np < 4; np++)
                    bcur[ks][np] = bnx[ks][np];
            __syncwarp();
        }
    }

    // ================= fused logits epilogue =================
    __syncthreads();   // all warps done with staging; reuse smem
    float* Ts   = (float*)dyn;               // [128][132] sxp tile
    float* xqT  = (float*)(dyn + XQT_OFF);   // [128][36]  xq half, transposed
    float* ssqh = (float*)(dyn + SSQ_OFF);   // [128]

#pragma unroll
    for (int t = 0; t < 2; t++) {
        int r0 = wm * 32 + t * 16 + (lane >> 2);
        int cl = wn * 64 + 2 * (lane & 3);
#pragma unroll
        for (int nf = 0; nf < 8; nf++) {
            *(float2*)&Ts[r0 * TS_PITCH + cl + nf * 8] =
                make_float2(c[t][nf][0], c[t][nf][1]);
            *(float2*)&Ts[(r0 + 8) * TS_PITCH + cl + nf * 8] =
                make_float2(c[t][nf][2], c[t][nf][3]);
        }
    }
    for (int i = tid; i < 32 * 128; i += 256) {
        int b = i & 31, k = i >> 5;
        xqT[k * XQT_PITCH + b] = g_xq[b * PROJ + bn + k];
    }
    __syncthreads();

    if (tid < 128) {
        float s = 0.f;
        const float4* row = (const float4*)&Ts[tid * TS_PITCH];
#pragma unroll
        for (int q = 0; q < 32; q++) {
            float4 v = row[q];
            s += v.x * v.x + v.y * v.y + v.z * v.z + v.w * v.w;
        }
        ssqh[tid] = s;
    }
    __syncthreads();

    {
        const int j0 = (tid & 31) * 4;        // 0..124
        const int b0 = (tid >> 5) * 4;        // 0..28
        float acc[4][4];
#pragma unroll
        for (int a = 0; a < 4; a++)
#pragma unroll
            for (int b = 0; b < 4; b++) acc[a][b] = 0.f;

        for (int k = 0; k < 128; k += 4) {
            float4 xv[4];
#pragma unroll
            for (int kk = 0; kk < 4; kk++)
                xv[kk] = *(const float4*)&xqT[(k + kk) * XQT_PITCH + b0];
#pragma unroll
            for (int jj = 0; jj < 4; jj++) {
                float4 tv = *(const float4*)&Ts[(j0 + jj) * TS_PITCH + k];
                float tk[4] = {tv.x, tv.y, tv.z, tv.w};
#pragma unroll
                for (int kk = 0; kk < 4; kk++) {
                    acc[jj][0] = fmaf(tk[kk], xv[kk].x, acc[jj][0]);
                    acc[jj][1] = fmaf(tk[kk], xv[kk].y, acc[jj][1]);
                    acc[jj][2] = fmaf(tk[kk], xv[kk].z, acc[jj][2]);
                    acc[jj][3] = fmaf(tk[kk], xv[kk].w, acc[jj][3]);
                }
            }
        }
        float4 sq = *(const float4*)&ssqh[j0];
        float sqa[4] = {sq.x, sq.y, sq.z, sq.w};
#pragma unroll
        for (int bb = 0; bb < 4; bb++) {
            float4 o;
            o.x = 2.f * acc[0][bb] - sqa[0];
            o.y = 2.f * acc[1][bb] - sqa[1];
            o.z = 2.f * acc[2][bb] - sqa[2];
            o.w = 2.f * acc[3][bb] - sqa[3];
            *(float4*)&g_lh[((size_t)hb * BATCH + b0 + bb) * NSUP + bs + j0] = o;
        }
    }
}

// ---------------------------------------------------------------------------
// K5: per-row softmax + class scatter + log (sums the two proj-half logits)
// ---------------------------------------------------------------------------
__global__ void __launch_bounds__(1024) k_out(const int* __restrict__ syw,
                                              float* __restrict__ out) {
    const int b = blockIdx.x;
    __shared__ float red[32];
    __shared__ float cls[NCLS];
    const int tid  = threadIdx.x;
    const int warp = tid >> 5, lane = tid & 31;

    for (int c = tid; c < NCLS; c += 1024) cls[c] = 0.f;

    const float* lr0 = g_lh + (size_t)b * NSUP;
    const float* lr1 = g_lh + (size_t)(BATCH + b) * NSUP;
    float l[8];
    float m = -3.4e38f;
#pragma unroll
    for (int q = 0; q < 8; q++) {
        int j = q * 1024 + tid;
        l[q] = lr0[j] + lr1[j];
        m = fmaxf(m, l[q]);
    }
#pragma unroll
    for (int o = 16; o; o >>= 1) m = fmaxf(m, __shfl_xor_sync(0xffffffffu, m, o));
    if (lane == 0) red[warp] = m;
    __syncthreads();
    if (warp == 0) {
        float v = red[lane];
#pragma unroll
        for (int o = 16; o; o >>= 1) v = fmaxf(v, __shfl_xor_sync(0xffffffffu, v, o));
        if (lane == 0) red[0] = v;
    }
    __syncthreads();
    m = red[0];
    __syncthreads();

    float e[8];
    float s = 0.f;
#pragma unroll
    for (int q = 0; q < 8; q++) {
        e[q] = expf(l[q] - m);
        s += e[q];
    }
#pragma unroll
    for (int o = 16; o; o >>= 1) s += __shfl_xor_sync(0xffffffffu, s, o);
    if (lane == 0) red[warp] = s;
    __syncthreads();
    if (warp == 0) {
        float v = red[lane];
#pragma unroll
        for (int o = 16; o; o >>= 1) v += __shfl_xor_sync(0xffffffffu, v, o);
        if (lane == 0) red[0] = v;
    }
    __syncthreads();
    const float invZ = 1.f / red[0];
    const int is64 = g_sy_is64;

#pragma unroll
    for (int q = 0; q < 8; q++) {
        int j = q * 1024 + tid;
        int cidx = is64 ? syw[2 * j] : syw[j];
        atomicAdd(&cls[cidx], e[q]);
    }
    __syncthreads();
    for (int c = tid; c < NCLS; c += 1024)
        out[b * NCLS + c] = logf(cls[c] * invZ + 1e-12f);
}

// ---------------------------------------------------------------------------
extern "C" void kernel_launch(void* const* d_in, const int* in_sizes, int n_in,
                              void* d_out, int out_size) {
    const float* x = nullptr;
    const float* sx = nullptr;
    const float* W = nullptr;
    const void*  sy = nullptr;
    for (int i = 0; i < n_in; i++) {
        switch (in_sizes[i]) {
            case BATCH * FEAT: x  = (const float*)d_in[i]; break;
            case NSUP * FEAT:  sx = (const float*)d_in[i]; break;
            case FEAT * PROJ:  W  = (const float*)d_in[i]; break;
            case NSUP:         sy = d_in[i];               break;
            default: break;
        }
    }
    float* out = (float*)d_out;

    static int smem_set = 0;
    if (!smem_set) {
        cudaFuncSetAttribute(k_sxp_hmma,
                             cudaFuncAttributeMaxDynamicSharedMemorySize, DYNB);
        smem_set = 1;
    }

    k_pre<<<289, 256>>>(W, x, (const unsigned*)sy);
    k_sxp_hmma<<<dim3(64, 2), 256, DYNB>>>(sx);
    k_out<<<BATCH, 1024>>>((const int*)sy, out);
}

// round 16
// speedup vs baseline: 1.1074x; 1.1074x over previous
#include <cuda_runtime.h>
#include <cuda_fp16.h>
#include <cstdint>

#define BATCH 32
#define FEAT  1024
#define PROJ  256
#define NSUP  8192
#define NCLS  1000

// ---- scratch (no allocations allowed; __device__ globals) ----
__device__ float g_xq[BATCH * PROJ];
__device__ float g_lh[2 * BATCH * NSUP];         // 2 MB: per-proj-half logits
__device__ int   g_sy_is64;
// B in mma-fragment order: idx = ks*512 + half*256 + wn*128 + np*32 + lane
__device__ uint4 g_wfrag[128 * 512];             // 1 MB

__device__ __forceinline__ uint32_t smem_u32(const void* p) {
    uint32_t a;
    asm("{ .reg .u64 t; cvta.to.shared.u64 t, %1; cvt.u32.u64 %0, t; }"
        : "=r"(a) : "l"(p));
    return a;
}

__device__ __forceinline__ uint32_t hl_pack(float a) {
    __half h = __float2half_rn(a);
    __half l = __float2half_rn(a - __half2float(h));
    __half2 p = __halves2half2(h, l);
    return *(uint32_t*)&p;
}

// packed fp32x2 FMA (proven on this toolchain in R1)
__device__ __forceinline__ unsigned long long ffma2(unsigned long long a,
                                                    unsigned long long b,
                                                    unsigned long long c) {
    unsigned long long d;
    asm("fma.rn.f32x2 %0, %1, %2, %3;" : "=l"(d) : "l"(a), "l"(b), "l"(c));
    return d;
}
__device__ __forceinline__ float ull_lo(unsigned long long v) {
    return __uint_as_float((unsigned)(v & 0xffffffffULL));
}
__device__ __forceinline__ float ull_hi(unsigned long long v) {
    return __uint_as_float((unsigned)(v >> 32));
}

// ---------------------------------------------------------------------------
// K_pre: one launch, three jobs (R13-exact).
//  blocks 0..255   : W[1024][256] -> g_wfrag (mma B-fragment order)
//  blocks 256..511 : xq = x @ W
//  block  512      : detect int64 vs int32 sy
// ---------------------------------------------------------------------------
__global__ void __launch_bounds__(256) k_pre(const float* __restrict__ W,
                                             const float* __restrict__ x,
                                             const unsigned* __restrict__ syw) {
    const int bx = blockIdx.x;
    if (bx < 256) {
        int idx  = bx * 256 + threadIdx.x;   // 0..65535
        int lane = idx & 31;
        int np   = (idx >> 5) & 3;
        int wn   = (idx >> 7) & 1;
        int hb   = (idx >> 8) & 1;
        int ks   = idx >> 9;                 // 0..127
        int n0   = hb * 128 + wn * 64 + np * 16 + (lane >> 2);
        int k0   = ks * 8 + (lane & 3);
        uint4 r;
        r.x = hl_pack(W[(size_t)k0 * PROJ + n0]);
        r.y = hl_pack(W[(size_t)(k0 + 4) * PROJ + n0]);
        r.z = hl_pack(W[(size_t)k0 * PROJ + n0 + 8]);
        r.w = hl_pack(W[(size_t)(k0 + 4) * PROJ + n0 + 8]);
        g_wfrag[idx] = r;
    } else if (bx < 512) {
        __shared__ float red[8][33];
        const int blk = bx - 256;            // 0..255
        const int b = blk >> 3, pc = blk & 7;
        const int lane = threadIdx.x & 31, ks = threadIdx.x >> 5;
        const int p = pc * 32 + lane;
        float a0 = 0.f, a1 = 0.f, a2 = 0.f, a3 = 0.f;
        const float* xr = x + b * FEAT + ks * 128;
        const float* wr = W + (size_t)(ks * 128) * PROJ + p;
#pragma unroll 8
        for (int k = 0; k < 128; k += 4) {
            a0 = fmaf(xr[k + 0], wr[(k + 0) * PROJ], a0);
            a1 = fmaf(xr[k + 1], wr[(k + 1) * PROJ], a1);
            a2 = fmaf(xr[k + 2], wr[(k + 2) * PROJ], a2);
            a3 = fmaf(xr[k + 3], wr[(k + 3) * PROJ], a3);
        }
        red[ks][lane] = (a0 + a1) + (a2 + a3);
        __syncthreads();
        if (ks == 0) {
            float s = 0.f;
#pragma unroll
            for (int q = 0; q < 8; q++) s += red[q][lane];
            g_xq[b * PROJ + p] = s;
        }
    } else {
        __shared__ int nz;
        if (threadIdx.x == 0) nz = 0;
        __syncthreads();
        int f = 0;
        for (int i = threadIdx.x; i < 4096; i += 256)
            if (syw[2 * i + 1] != 0u) f = 1;
        if (f) atomicOr(&nz, 1);
        __syncthreads();
        if (threadIdx.x == 0) g_sy_is64 = (nz == 0) ? 1 : 0;
    }
}

// ---------------------------------------------------------------------------
// K2: sxp GEMM (HMMA fp16 2-slot K-doubling) + fused logits epilogue.
// Mainloop = R11 exact (warp-private A staging, no CTA barriers).
// Epilogue: Ts spilled TRANSPOSED [k][j], xq stored DUPLICATED (x,x) pairs
// with EVEN pitch (16B alignment fix), mini-GEMM via fma.rn.f32x2.
// ---------------------------------------------------------------------------
#define BANDB  2560                   // 32 rows * 80 B per warp per stage
#define STG2B  20480                  // 8 warps * BANDB
#define TS2_PITCH 132                 // floats per k-row of Ts_T (528 B, 16-div)
#define XQD_OFF   67584               // 128*132*4
#define XQD_PITCH 34                  // ulls per k-row (272 B, 16-div)  [FIX]
#define SSQ_OFF   102400              // XQD_OFF + 128*34*8
#define DYNB      103424

__global__ void __launch_bounds__(256, 1)
k_sxp_hmma(const float* __restrict__ sx) {
    extern __shared__ __align__(16) char dyn[];

    const int tid  = threadIdx.x;
    const int lane = tid & 31;
    const int wid  = tid >> 5;
    const int wm   = wid & 3;        // M block (32 rows)
    const int wn   = wid >> 2;       // N block (64 cols)
    const int bs   = blockIdx.x * 128;
    const int bn   = blockIdx.y * 128;
    const int hb   = blockIdx.y;

    const uint32_t sbase = smem_u32(dyn);
    const uint32_t pw_u32[2] = {sbase + (uint32_t)wid * BANDB,
                                sbase + STG2B + (uint32_t)wid * BANDB};
    char* pw_ptr[2] = {dyn + wid * BANDB, dyn + STG2B + wid * BANDB};

    const int arow = lane >> 2;      // 0..7
    const int aq   = lane & 3;       // 0..3
    const float* aptr[4];
#pragma unroll
    for (int i = 0; i < 4; i++)
        aptr[i] = sx + (size_t)(bs + wm * 32 + i * 8 + arow) * FEAT + aq * 4;
    const uint32_t sts_off = (uint32_t)(arow * 80 + aq * 16);

    const uint4* bbase = g_wfrag + hb * 256 + wn * 128 + lane;

    float c[2][8][4];
#pragma unroll
    for (int t = 0; t < 2; t++)
#pragma unroll
        for (int n = 0; n < 8; n++)
#pragma unroll
            for (int e = 0; e < 4; e++) c[t][n][e] = 0.f;

    const int grp  = lane >> 3;
    const int rsel = lane & 7;
    const int a_row_off = ((grp & 1) << 3) + rsel;
    const int a_u_off   = (grp >> 1) & 1;

    auto expand = [](float4 v) -> uint4 {
        __half h0 = __float2half_rn(v.x), h1 = __float2half_rn(v.y);
        __half h2 = __float2half_rn(v.z), h3 = __float2half_rn(v.w);
        __half2 p0 = __halves2half2(h0, __float2half_rn(v.x - __half2float(h0)));
        __half2 p1 = __halves2half2(h1, __float2half_rn(v.y - __half2float(h1)));
        __half2 p2 = __halves2half2(h2, __float2half_rn(v.z - __half2float(h2)));
        __half2 p3 = __halves2half2(h3, __float2half_rn(v.w - __half2float(h3)));
        return make_uint4(*(uint32_t*)&p0, *(uint32_t*)&p1,
                          *(uint32_t*)&p2, *(uint32_t*)&p3);
    };

    uint4 bcur[2][4];    // [ks][np]

    // ---- prologue: chunk 0 into stage 0 ----
    {
        float4 av[4];
#pragma unroll
        for (int i = 0; i < 4; i++) av[i] = *(const float4*)(aptr[i]);
#pragma unroll
        for (int i = 0; i < 4; i++)
            *(uint4*)(pw_ptr[0] + i * 8 * 80 + sts_off) = expand(av[i]);
#pragma unroll
        for (int ks = 0; ks < 2; ks++)
#pragma unroll
            for (int np = 0; np < 4; np++)
                bcur[ks][np] = bbase[ks * 512 + np * 32];
    }
    __syncwarp();

#pragma unroll 2
    for (int ch = 0; ch < 64; ch++) {
        const int s = ch & 1;
        float4 av[4];
        uint4  bnx[2][4];
        if (ch < 63) {
            const int k0 = (ch + 1) * 16;
#pragma unroll
            for (int i = 0; i < 4; i++)
                av[i] = *(const float4*)(aptr[i] + k0);
#pragma unroll
            for (int ks = 0; ks < 2; ks++)
#pragma unroll
                for (int np = 0; np < 4; np++)
                    bnx[ks][np] = bbase[(2 * (ch + 1) + ks) * 512 + np * 32];
        }

#pragma unroll
        for (int ks = 0; ks < 2; ks++) {
            uint32_t af[2][4];
#pragma unroll
            for (int t = 0; t < 2; t++) {
                int row = t * 16 + a_row_off;
                uint32_t addr = pw_u32[s] + (uint32_t)(row * 80 + (2 * ks + a_u_off) * 16);
                asm volatile(
                    "ldmatrix.sync.aligned.m8n8.x4.shared.b16 {%0,%1,%2,%3}, [%4];"
                    : "=r"(af[t][0]), "=r"(af[t][1]), "=r"(af[t][2]), "=r"(af[t][3])
                    : "r"(addr));
            }
#pragma unroll
            for (int t = 0; t < 2; t++)
#pragma unroll
                for (int nf = 0; nf < 8; nf++) {
                    const uint4& bq = bcur[ks][nf >> 1];
                    uint32_t b0 = (nf & 1) ? bq.z : bq.x;
                    uint32_t b1 = (nf & 1) ? bq.w : bq.y;
                    asm volatile(
                        "mma.sync.aligned.m16n8k16.row.col.f32.f16.f16.f32 "
                        "{%0,%1,%2,%3}, {%4,%5,%6,%7}, {%8,%9}, {%0,%1,%2,%3};"
                        : "+f"(c[t][nf][0]), "+f"(c[t][nf][1]),
                          "+f"(c[t][nf][2]), "+f"(c[t][nf][3])
                        : "r"(af[t][0]), "r"(af[t][1]), "r"(af[t][2]), "r"(af[t][3]),
                          "r"(b0), "r"(b1));
                }
        }

        if (ch < 63) {
            const int ns = s ^ 1;
#pragma unroll
            for (int i = 0; i < 4; i++)
                *(uint4*)(pw_ptr[ns] + i * 8 * 80 + sts_off) = expand(av[i]);
#pragma unroll
            for (int ks = 0; ks < 2; ks++)
#pragma unroll
                for (int np = 0; np < 4; np++)
                    bcur[ks][np] = bnx[ks][np];
            __syncwarp();
        }
    }

    // ================= fused logits epilogue (f32x2) =================
    __syncthreads();   // all warps done with staging; reuse smem
    float* TsT  = (float*)dyn;                            // [128 k][132] (col j)
    unsigned long long* xqd = (unsigned long long*)(dyn + XQD_OFF); // [128 k][34]
    float* ssqh = (float*)(dyn + SSQ_OFF);                // [128]

    // spill fragments TRANSPOSED: TsT[k = local proj][j = local support]
#pragma unroll
    for (int t = 0; t < 2; t++) {
        int r0 = wm * 32 + t * 16 + (lane >> 2);
        int cl = wn * 64 + 2 * (lane & 3);
#pragma unroll
        for (int nf = 0; nf < 8; nf++) {
            int k0 = cl + nf * 8;
            TsT[(k0 + 0) * TS2_PITCH + r0]     = c[t][nf][0];
            TsT[(k0 + 1) * TS2_PITCH + r0]     = c[t][nf][1];
            TsT[(k0 + 0) * TS2_PITCH + r0 + 8] = c[t][nf][2];
            TsT[(k0 + 1) * TS2_PITCH + r0 + 8] = c[t][nf][3];
        }
    }
    // xq half, duplicated pairs: xqd[k][b] = (x, x)
    for (int i = tid; i < 32 * 128; i += 256) {
        int b = i & 31, k = i >> 5;
        float v = g_xq[b * PROJ + bn + k];
        unsigned long long d =
            ((unsigned long long)__float_as_uint(v) << 32) | __float_as_uint(v);
        xqd[k * XQD_PITCH + b] = d;
    }
    __syncthreads();

    // ssq_half[j]: column sum of squares over k
    if (tid < 128) {
        float s = 0.f;
#pragma unroll 8
        for (int k = 0; k < 128; k++) {
            float v = TsT[k * TS2_PITCH + tid];
            s = fmaf(v, v, s);
        }
        ssqh[tid] = s;
    }
    __syncthreads();

    // mini-GEMM: 4 j x 4 b per thread, f32x2 over j-pairs.
    {
        const int j0 = (tid & 31) * 4;        // 0..124
        const int b0 = (tid >> 5) * 4;        // 0..28 (even -> 16B aligned)
        unsigned long long acc2[2][4];        // [j-pair][b]
#pragma unroll
        for (int jp = 0; jp < 2; jp++)
#pragma unroll
            for (int bb = 0; bb < 4; bb++) acc2[jp][bb] = 0ULL;

#pragma unroll 4
        for (int k = 0; k < 128; k++) {
            ulonglong2 tv = *(const ulonglong2*)&TsT[k * TS2_PITCH + j0];
            unsigned long long tp[2] = {tv.x, tv.y};
            ulonglong2 xv01 = *(const ulonglong2*)&xqd[k * XQD_PITCH + b0];
            ulonglong2 xv23 = *(const ulonglong2*)&xqd[k * XQD_PITCH + b0 + 2];
            unsigned long long xp[4] = {xv01.x, xv01.y, xv23.x, xv23.y};
#pragma unroll
            for (int jp = 0; jp < 2; jp++)
#pragma unroll
                for (int bb = 0; bb < 4; bb++)
                    acc2[jp][bb] = ffma2(tp[jp], xp[bb], acc2[jp][bb]);
        }

        float4 sq = *(const float4*)&ssqh[j0];
        float sqa[4] = {sq.x, sq.y, sq.z, sq.w};
#pragma unroll
        for (int bb = 0; bb < 4; bb++) {
            float4 o;
            o.x = 2.f * ull_lo(acc2[0][bb]) - sqa[0];
            o.y = 2.f * ull_hi(acc2[0][bb]) - sqa[1];
            o.z = 2.f * ull_lo(acc2[1][bb]) - sqa[2];
            o.w = 2.f * ull_hi(acc2[1][bb]) - sqa[3];
            *(float4*)&g_lh[((size_t)hb * BATCH + b0 + bb) * NSUP + bs + j0] = o;
        }
    }
}

// ---------------------------------------------------------------------------
// K5: per-row softmax + class scatter + log (sums the two proj-half logits)
// ---------------------------------------------------------------------------
__global__ void __launch_bounds__(1024) k_out(const int* __restrict__ syw,
                                              float* __restrict__ out) {
    const int b = blockIdx.x;
    __shared__ float red[32];
    __shared__ float cls[NCLS];
    const int tid  = threadIdx.x;
    const int warp = tid >> 5, lane = tid & 31;

    for (int c = tid; c < NCLS; c += 1024) cls[c] = 0.f;

    const float* lr0 = g_lh + (size_t)b * NSUP;
    const float* lr1 = g_lh + (size_t)(BATCH + b) * NSUP;
    float l[8];
    float m = -3.4e38f;
#pragma unroll
    for (int q = 0; q < 8; q++) {
        int j = q * 1024 + tid;
        l[q] = lr0[j] + lr1[j];
        m = fmaxf(m, l[q]);
    }
#pragma unroll
    for (int o = 16; o; o >>= 1) m = fmaxf(m, __shfl_xor_sync(0xffffffffu, m, o));
    if (lane == 0) red[warp] = m;
    __syncthreads();
    if (warp == 0) {
        float v = red[lane];
#pragma unroll
        for (int o = 16; o; o >>= 1) v = fmaxf(v, __shfl_xor_sync(0xffffffffu, v, o));
        if (lane == 0) red[0] = v;
    }
    __syncthreads();
    m = red[0];
    __syncthreads();

    float e[8];
    float s = 0.f;
#pragma unroll
    for (int q = 0; q < 8; q++) {
        e[q] = expf(l[q] - m);
        s += e[q];
    }
#pragma unroll
    for (int o = 16; o; o >>= 1) s += __shfl_xor_sync(0xffffffffu, s, o);
    if (lane == 0) red[warp] = s;
    __syncthreads();
    if (warp == 0) {
        float v = red[lane];
#pragma unroll
        for (int o = 16; o; o >>= 1) v += __shfl_xor_sync(0xffffffffu, v, o);
        if (lane == 0) red[0] = v;
    }
    __syncthreads();
    const float invZ = 1.f / red[0];
    const int is64 = g_sy_is64;

#pragma unroll
    for (int q = 0; q < 8; q++) {
        int j = q * 1024 + tid;
        int cidx = is64 ? syw[2 * j] : syw[j];
        atomicAdd(&cls[cidx], e[q]);
    }
    __syncthreads();
    for (int c = tid; c < NCLS; c += 1024)
        out[b * NCLS + c] = logf(cls[c] * invZ + 1e-12f);
}

// ---------------------------------------------------------------------------
extern "C" void kernel_launch(void* const* d_in, const int* in_sizes, int n_in,
                              void* d_out, int out_size) {
    const float* x = nullptr;
    const float* sx = nullptr;
    const float* W = nullptr;
    const void*  sy = nullptr;
    for (int i = 0; i < n_in; i++) {
        switch (in_sizes[i]) {
            case BATCH * FEAT: x  = (const float*)d_in[i]; break;
            case NSUP * FEAT:  sx = (const float*)d_in[i]; break;
            case FEAT * PROJ:  W  = (const float*)d_in[i]; break;
            case NSUP:         sy = d_in[i];               break;
            default: break;
        }
    }
    float* out = (float*)d_out;

    static int smem_set = 0;
    if (!smem_set) {
        cudaFuncSetAttribute(k_sxp_hmma,
                             cudaFuncAttributeMaxDynamicSharedMemorySize, DYNB);
        smem_set = 1;
    }

    k_pre<<<513, 256>>>(W, x, (const unsigned*)sy);
    k_sxp_hmma<<<dim3(64, 2), 256, DYNB>>>(sx);
    k_out<<<BATCH, 1024>>>((const int*)sy, out);
}